// round 16
// baseline (speedup 1.0000x reference)
#include <cuda_runtime.h>
#include <mma.h>
#include <math.h>

using namespace nvcuda;

#define N_NODES 8192
#define E_EDGES 131072
#define C_DIM   512
#define H_HEADS 8
#define D_HEAD  64
#define K_RANK  256

// ---------------- scratch (device globals; no allocation allowed) ----------
__device__ float d_Q   [N_NODES * C_DIM];
__device__ float d_Kmat[N_NODES * C_DIM];
__device__ float d_Vmat[N_NODES * C_DIM];
__device__ float d_Att [N_NODES * C_DIM];
__device__ float d_pK  [H_HEADS * K_RANK * D_HEAD];
__device__ float d_pV  [H_HEADS * K_RANK * D_HEAD];

// ============================================================================
// Generic linear: out[m, :512] = X[m,:512] @ W^T + bias, optional LN+residual.
// BM=32 rows per CTA, BN=512 (full row -> LN fully in-CTA).
// 8 warps: 2 warp-rows x 4 warp-cols, each warp = 1x8 fragments of 16x16.
// tf32 wmma m16n16k8, accum fp32. Epilogue staged through SMEM (ld=520).
// ============================================================================
template <bool DO_LN>
__global__ void linear512_kernel(const float* __restrict__ X,
                                 const float* __restrict__ W,      // (512 out, 512 in) row-major
                                 const float* __restrict__ bias,
                                 const float* __restrict__ resid,
                                 const float* __restrict__ gamma,
                                 const float* __restrict__ beta,
                                 float* __restrict__ out)
{
    extern __shared__ float sm[];            // 32 x 520 floats
    const int ldt = 520;
    const int wid     = threadIdx.x >> 5;
    const int lane    = threadIdx.x & 31;
    const int warpRow = wid >> 2;            // 0..1
    const int warpCol = wid & 3;             // 0..3
    const int row0    = blockIdx.x * 32;

    wmma::fragment<wmma::accumulator, 16, 16, 8, float> acc[8];
    #pragma unroll
    for (int f = 0; f < 8; f++) wmma::fill_fragment(acc[f], 0.0f);

    const float* Abase = X + (size_t)(row0 + warpRow * 16) * C_DIM;

    for (int k = 0; k < C_DIM; k += 8) {
        wmma::fragment<wmma::matrix_a, 16, 16, 8, wmma::precision::tf32, wmma::row_major> a;
        wmma::load_matrix_sync(a, Abase + k, C_DIM);
        #pragma unroll
        for (int t = 0; t < a.num_elements; t++) a.x[t] = wmma::__float_to_tf32(a.x[t]);
        #pragma unroll
        for (int f = 0; f < 8; f++) {
            const int j0 = warpCol * 128 + f * 16;
            wmma::fragment<wmma::matrix_b, 16, 16, 8, wmma::precision::tf32, wmma::col_major> b;
            // B(k,j) = W[j*512 + k]  (W^T), col_major with ldm=512
            wmma::load_matrix_sync(b, W + (size_t)j0 * C_DIM + k, C_DIM);
            #pragma unroll
            for (int t = 0; t < b.num_elements; t++) b.x[t] = wmma::__float_to_tf32(b.x[t]);
            wmma::mma_sync(acc[f], a, b, acc[f]);
        }
    }

    #pragma unroll
    for (int f = 0; f < 8; f++)
        wmma::store_matrix_sync(&sm[(warpRow * 16) * ldt + warpCol * 128 + f * 16],
                                acc[f], ldt, wmma::mem_row_major);
    __syncthreads();

    // Epilogue: each warp handles 4 rows; 16 floats per lane held in registers.
    #pragma unroll
    for (int rr = 0; rr < 4; rr++) {
        const int r = wid * 4 + rr;
        const size_t grow = (size_t)(row0 + r);
        float4 v[4];
        #pragma unroll
        for (int i = 0; i < 4; i++) {
            const int c4 = lane + i * 32;     // float4 index; col = 4*c4
            float4 t  = *(const float4*)&sm[r * ldt + c4 * 4];
            float4 bb = *(const float4*)&bias[c4 * 4];
            v[i] = make_float4(t.x + bb.x, t.y + bb.y, t.z + bb.z, t.w + bb.w);
        }
        if (DO_LN) {
            float s = 0.f, sq = 0.f;
            #pragma unroll
            for (int i = 0; i < 4; i++) {
                s  += v[i].x + v[i].y + v[i].z + v[i].w;
                sq += v[i].x * v[i].x + v[i].y * v[i].y + v[i].z * v[i].z + v[i].w * v[i].w;
            }
            #pragma unroll
            for (int o = 16; o > 0; o >>= 1) {
                s  += __shfl_xor_sync(0xffffffffu, s,  o);
                sq += __shfl_xor_sync(0xffffffffu, sq, o);
            }
            const float mu   = s * (1.0f / 512.0f);
            const float var  = sq * (1.0f / 512.0f) - mu * mu;
            const float rstd = rsqrtf(var + 1e-5f);
            #pragma unroll
            for (int i = 0; i < 4; i++) {
                const int c4 = lane + i * 32;
                float4 g  = *(const float4*)&gamma[c4 * 4];
                float4 be = *(const float4*)&beta [c4 * 4];
                float4 rz = *(const float4*)&resid[grow * C_DIM + c4 * 4];
                float4 o4;
                o4.x = (v[i].x - mu) * rstd * g.x + be.x + rz.x;
                o4.y = (v[i].y - mu) * rstd * g.y + be.y + rz.y;
                o4.z = (v[i].z - mu) * rstd * g.z + be.z + rz.z;
                o4.w = (v[i].w - mu) * rstd * g.w + be.w + rz.w;
                *(float4*)&out[grow * C_DIM + c4 * 4] = o4;
            }
        } else {
            #pragma unroll
            for (int i = 0; i < 4; i++) {
                const int c4 = lane + i * 32;
                *(float4*)&out[grow * C_DIM + c4 * 4] = v[i];
            }
        }
    }
}

// ============================================================================
// Linformer projection: outP[h, r, d] = sum_n P[h, r, n] * S[n, h*64 + d]
// P: (H, 256, 8192), S: QKV scratch (N, 512). Grid (256/32, H), 8 warps,
// warp tile 16x16, K-loop over N in steps of 8.
// ============================================================================
__global__ void proj_kernel(const float* __restrict__ P,
                            const float* __restrict__ S,
                            float* __restrict__ outP)
{
    const int wid     = threadIdx.x >> 5;
    const int warpRow = wid >> 2;            // 0..1
    const int warpCol = wid & 3;             // 0..3
    const int h  = blockIdx.y;
    const int r0 = blockIdx.x * 32 + warpRow * 16;

    wmma::fragment<wmma::accumulator, 16, 16, 8, float> acc;
    wmma::fill_fragment(acc, 0.0f);

    const float* Abase = P + ((size_t)h * K_RANK + r0) * N_NODES;
    const float* Bbase = S + h * D_HEAD + warpCol * 16;

    for (int k = 0; k < N_NODES; k += 8) {
        wmma::fragment<wmma::matrix_a, 16, 16, 8, wmma::precision::tf32, wmma::row_major> a;
        wmma::load_matrix_sync(a, Abase + k, N_NODES);
        #pragma unroll
        for (int t = 0; t < a.num_elements; t++) a.x[t] = wmma::__float_to_tf32(a.x[t]);
        wmma::fragment<wmma::matrix_b, 16, 16, 8, wmma::precision::tf32, wmma::row_major> b;
        wmma::load_matrix_sync(b, Bbase + (size_t)k * C_DIM, C_DIM);
        #pragma unroll
        for (int t = 0; t < b.num_elements; t++) b.x[t] = wmma::__float_to_tf32(b.x[t]);
        wmma::mma_sync(acc, a, b, acc);
    }
    wmma::store_matrix_sync(outP + ((size_t)h * K_RANK + r0) * D_HEAD + warpCol * 16,
                            acc, D_HEAD, wmma::mem_row_major);
}

// ============================================================================
// Attention: per (head, 64-node block) CTA.
//   scores = Q_tile(64x64) @ pK^T(64x256) * 0.125 -> softmax over 256
//   out    = attn(64x256) @ pV(256x64)
// pK, pV resident in SMEM (64 KB each); scores tile 64 x 272 in SMEM.
// ============================================================================
__global__ void attn_kernel(const float* __restrict__ Q,
                            const float* __restrict__ pK,
                            const float* __restrict__ pV,
                            float* __restrict__ attnout)
{
    extern __shared__ float smA[];
    float* pKs = smA;                                // 256*64
    float* pVs = smA + K_RANK * D_HEAD;              // 256*64
    float* sc  = smA + 2 * K_RANK * D_HEAD;          // 64 x 272
    const int lds = 272;

    const int h   = blockIdx.y;
    const int n0  = blockIdx.x * 64;
    const int tid = threadIdx.x;
    const int wid = tid >> 5, lane = tid & 31;

    {   // stage pK, pV
        const float4* s1 = (const float4*)(pK + (size_t)h * K_RANK * D_HEAD);
        const float4* s2 = (const float4*)(pV + (size_t)h * K_RANK * D_HEAD);
        float4* d1 = (float4*)pKs;
        float4* d2 = (float4*)pVs;
        for (int i = tid; i < K_RANK * D_HEAD / 4; i += 256) { d1[i] = s1[i]; d2[i] = s2[i]; }
    }
    __syncthreads();

    // ---- GEMM1: scores (64 x 256). 4 warp-rows x 2 warp-cols(128 each) ----
    {
        const int wr = wid >> 1;    // 0..3
        const int wc = wid & 1;     // 0..1
        wmma::fragment<wmma::accumulator, 16, 16, 8, float> acc[8];
        #pragma unroll
        for (int f = 0; f < 8; f++) wmma::fill_fragment(acc[f], 0.0f);
        const float* Abase = Q + (size_t)(n0 + wr * 16) * C_DIM + h * D_HEAD;
        for (int k = 0; k < D_HEAD; k += 8) {
            wmma::fragment<wmma::matrix_a, 16, 16, 8, wmma::precision::tf32, wmma::row_major> a;
            wmma::load_matrix_sync(a, Abase + k, C_DIM);
            #pragma unroll
            for (int t = 0; t < a.num_elements; t++) a.x[t] = wmma::__float_to_tf32(a.x[t]);
            #pragma unroll
            for (int f = 0; f < 8; f++) {
                const int j0 = wc * 128 + f * 16;
                wmma::fragment<wmma::matrix_b, 16, 16, 8, wmma::precision::tf32, wmma::col_major> b;
                wmma::load_matrix_sync(b, pKs + j0 * D_HEAD + k, D_HEAD);
                #pragma unroll
                for (int t = 0; t < b.num_elements; t++) b.x[t] = wmma::__float_to_tf32(b.x[t]);
                wmma::mma_sync(acc[f], a, b, acc[f]);
            }
        }
        #pragma unroll
        for (int f = 0; f < 8; f++)
            wmma::store_matrix_sync(&sc[(wr * 16) * lds + wc * 128 + f * 16],
                                    acc[f], lds, wmma::mem_row_major);
    }
    __syncthreads();

    // ---- softmax over 256 per row (scale 1/8, max-subtract, normalize) ----
    for (int r = wid; r < 64; r += 8) {
        float vals[8];
        float mx = -1e30f;
        #pragma unroll
        for (int i = 0; i < 8; i++) {
            vals[i] = sc[r * lds + lane + i * 32] * 0.125f;
            mx = fmaxf(mx, vals[i]);
        }
        #pragma unroll
        for (int o = 16; o > 0; o >>= 1) mx = fmaxf(mx, __shfl_xor_sync(0xffffffffu, mx, o));
        float ssum = 0.f;
        #pragma unroll
        for (int i = 0; i < 8; i++) { vals[i] = __expf(vals[i] - mx); ssum += vals[i]; }
        #pragma unroll
        for (int o = 16; o > 0; o >>= 1) ssum += __shfl_xor_sync(0xffffffffu, ssum, o);
        const float inv = 1.0f / ssum;
        #pragma unroll
        for (int i = 0; i < 8; i++) sc[r * lds + lane + i * 32] = vals[i] * inv;
    }
    __syncthreads();

    // ---- GEMM2: out (64 x 64) = attn @ pV. 4 warp-rows x 2 warp-cols(32) ----
    {
        const int wr = wid >> 1;    // 0..3
        const int wc = wid & 1;     // 0..1
        wmma::fragment<wmma::accumulator, 16, 16, 8, float> acc[2];
        wmma::fill_fragment(acc[0], 0.0f);
        wmma::fill_fragment(acc[1], 0.0f);
        const float* Abase = sc + (wr * 16) * lds;
        for (int k = 0; k < K_RANK; k += 8) {
            wmma::fragment<wmma::matrix_a, 16, 16, 8, wmma::precision::tf32, wmma::row_major> a;
            wmma::load_matrix_sync(a, Abase + k, lds);
            #pragma unroll
            for (int t = 0; t < a.num_elements; t++) a.x[t] = wmma::__float_to_tf32(a.x[t]);
            #pragma unroll
            for (int f = 0; f < 2; f++) {
                wmma::fragment<wmma::matrix_b, 16, 16, 8, wmma::precision::tf32, wmma::row_major> b;
                wmma::load_matrix_sync(b, pVs + k * D_HEAD + wc * 32 + f * 16, D_HEAD);
                #pragma unroll
                for (int t = 0; t < b.num_elements; t++) b.x[t] = wmma::__float_to_tf32(b.x[t]);
                wmma::mma_sync(acc[f], a, b, acc[f]);
            }
        }
        #pragma unroll
        for (int f = 0; f < 2; f++)
            wmma::store_matrix_sync(attnout + (size_t)(n0 + wr * 16) * C_DIM
                                            + h * D_HEAD + wc * 32 + f * 16,
                                    acc[f], C_DIM, wmma::mem_row_major);
    }
}

// ============================================================================
// Node epilogue: out = LN(attnout) * g + b + node_feats. One warp per row.
// ============================================================================
__global__ void ln_resid_kernel(const float* __restrict__ X,
                                const float* __restrict__ resid,
                                const float* __restrict__ gamma,
                                const float* __restrict__ beta,
                                float* __restrict__ out)
{
    const int wid = threadIdx.x >> 5, lane = threadIdx.x & 31;
    const size_t row = (size_t)blockIdx.x * 8 + wid;
    float4 v[4];
    float s = 0.f, sq = 0.f;
    #pragma unroll
    for (int i = 0; i < 4; i++) {
        const int c4 = lane + i * 32;
        v[i] = *(const float4*)&X[row * C_DIM + c4 * 4];
        s  += v[i].x + v[i].y + v[i].z + v[i].w;
        sq += v[i].x * v[i].x + v[i].y * v[i].y + v[i].z * v[i].z + v[i].w * v[i].w;
    }
    #pragma unroll
    for (int o = 16; o > 0; o >>= 1) {
        s  += __shfl_xor_sync(0xffffffffu, s,  o);
        sq += __shfl_xor_sync(0xffffffffu, sq, o);
    }
    const float mu   = s * (1.0f / 512.0f);
    const float var  = sq * (1.0f / 512.0f) - mu * mu;
    const float rstd = rsqrtf(var + 1e-5f);
    #pragma unroll
    for (int i = 0; i < 4; i++) {
        const int c4 = lane + i * 32;
        float4 g  = *(const float4*)&gamma[c4 * 4];
        float4 be = *(const float4*)&beta [c4 * 4];
        float4 rz = *(const float4*)&resid[row * C_DIM + c4 * 4];
        float4 o4;
        o4.x = (v[i].x - mu) * rstd * g.x + be.x + rz.x;
        o4.y = (v[i].y - mu) * rstd * g.y + be.y + rz.y;
        o4.z = (v[i].z - mu) * rstd * g.z + be.z + rz.z;
        o4.w = (v[i].w - mu) * rstd * g.w + be.w + rz.w;
        *(float4*)&out[row * C_DIM + c4 * 4] = o4;
    }
}

// ============================================================================
extern "C" void kernel_launch(void* const* d_in, const int* in_sizes, int n_in,
                              void* d_out, int out_size)
{
    const float* node = (const float*)d_in[0];
    const float* edge = (const float*)d_in[1];
    const float* Wq   = (const float*)d_in[2];
    const float* bq   = (const float*)d_in[3];
    const float* Wk   = (const float*)d_in[4];
    const float* bk   = (const float*)d_in[5];
    const float* Wv   = (const float*)d_in[6];
    const float* bv   = (const float*)d_in[7];
    const float* We   = (const float*)d_in[8];
    const float* be   = (const float*)d_in[9];
    const float* Ep   = (const float*)d_in[10];
    const float* Fp   = (const float*)d_in[11];
    const float* lng  = (const float*)d_in[12];
    const float* lnb  = (const float*)d_in[13];
    const float* leg  = (const float*)d_in[14];
    const float* leb  = (const float*)d_in[15];
    float* out = (float*)d_out;

    float *pQ, *pK_, *pV_, *pAt, *ppK, *ppV;
    cudaGetSymbolAddress((void**)&pQ,  d_Q);
    cudaGetSymbolAddress((void**)&pK_, d_Kmat);
    cudaGetSymbolAddress((void**)&pV_, d_Vmat);
    cudaGetSymbolAddress((void**)&pAt, d_Att);
    cudaGetSymbolAddress((void**)&ppK, d_pK);
    cudaGetSymbolAddress((void**)&ppV, d_pV);

    const int SM_LIN = 32 * 520 * (int)sizeof(float);                       // 66560
    const int SM_ATT = (2 * K_RANK * D_HEAD + 64 * 272) * (int)sizeof(float); // 200704
    cudaFuncSetAttribute(linear512_kernel<false>, cudaFuncAttributeMaxDynamicSharedMemorySize, SM_LIN);
    cudaFuncSetAttribute(linear512_kernel<true>,  cudaFuncAttributeMaxDynamicSharedMemorySize, SM_LIN);
    cudaFuncSetAttribute(attn_kernel,             cudaFuncAttributeMaxDynamicSharedMemorySize, SM_ATT);

    // 1) QKV projections (N x 512 each)
    linear512_kernel<false><<<N_NODES / 32, 256, SM_LIN>>>(node, Wq, bq, nullptr, nullptr, nullptr, pQ);
    linear512_kernel<false><<<N_NODES / 32, 256, SM_LIN>>>(node, Wk, bk, nullptr, nullptr, nullptr, pK_);
    linear512_kernel<false><<<N_NODES / 32, 256, SM_LIN>>>(node, Wv, bv, nullptr, nullptr, nullptr, pV_);

    // 2) Linformer projections pK = Ep @ Kh, pV = Fp @ Vh  (H, 256, 64)
    proj_kernel<<<dim3(K_RANK / 32, H_HEADS), 256>>>(Ep, pK_, ppK);
    proj_kernel<<<dim3(K_RANK / 32, H_HEADS), 256>>>(Fp, pV_, ppV);

    // 3) Attention per (head, 64-row block)
    attn_kernel<<<dim3(N_NODES / 64, H_HEADS), 256, SM_ATT>>>(pQ, ppK, ppV, pAt);

    // 4) Node output: LN(attn) + node_feats -> out[0 : N*512)
    ln_resid_kernel<<<N_NODES / 8, 256>>>(pAt, node, lng, lnb, out);

    // 5) Edge path: LN(edge @ We^T + be) + edge_feats -> out[N*512 : )
    linear512_kernel<true><<<E_EDGES / 32, 256, SM_LIN>>>(
        edge, We, be, edge, leg, leb, out + (size_t)N_NODES * C_DIM);
}

// round 17
// speedup vs baseline: 2.4292x; 2.4292x over previous
#include <cuda_runtime.h>
#include <mma.h>
#include <math.h>

using namespace nvcuda;

#define N_NODES 8192
#define E_EDGES 131072
#define C_DIM   512
#define H_HEADS 8
#define D_HEAD  64
#define K_RANK  256
#define NSPLIT  16          // n-chunks for split-K Linformer projection

// ---------------- scratch (device globals; no allocation allowed) ----------
__device__ __align__(16) float d_Q   [N_NODES * C_DIM];
__device__ __align__(16) float d_Kmat[N_NODES * C_DIM];
__device__ __align__(16) float d_Vmat[N_NODES * C_DIM];
__device__ __align__(16) float d_Att [N_NODES * C_DIM];
__device__ __align__(16) float d_pK  [H_HEADS * K_RANK * D_HEAD];
__device__ __align__(16) float d_pV  [H_HEADS * K_RANK * D_HEAD];
__device__ __align__(16) float d_partK[NSPLIT * H_HEADS * K_RANK * D_HEAD];
__device__ __align__(16) float d_partV[NSPLIT * H_HEADS * K_RANK * D_HEAD];

// ---------------- cp.async helpers -----------------------------------------
__device__ __forceinline__ void cp_async16(float* smem_dst, const float* gsrc) {
    unsigned s = (unsigned)__cvta_generic_to_shared(smem_dst);
    asm volatile("cp.async.cg.shared.global [%0], [%1], 16;\n" :: "r"(s), "l"(gsrc));
}
#define CP_COMMIT() asm volatile("cp.async.commit_group;\n" ::: "memory")
#define CP_WAIT(n)  asm volatile("cp.async.wait_group %0;\n" :: "n"(n) : "memory")

// ============================================================================
// linear512 v2: out[m,:512] = X[m,:512] @ W^T + bias (+ optional LN + resid).
// BM=64, BN=512, BK=16. 512 threads = 16 warps (4 warp-rows x 4 warp-cols),
// warp tile 16x128 = 8 fragments. X/W tiles staged via cp.async, double buf.
// Epilogue staged through SMEM (ld=520) for in-CTA LayerNorm.
// ============================================================================
template <bool DO_LN>
__global__ void __launch_bounds__(512, 1)
linear512_kernel(const float* __restrict__ X,
                 const float* __restrict__ W,      // (512 out, 512 in) row-major
                 const float* __restrict__ bias,
                 const float* __restrict__ resid,
                 const float* __restrict__ gamma,
                 const float* __restrict__ beta,
                 float* __restrict__ out)
{
    extern __shared__ float sm[];
    const int ldX = 24, ldW = 24;
    float* Xs = sm;                      // 2 * 64*24  = 3072 floats
    float* Ws = sm + 2 * 64 * ldX;       // 2 * 512*24 = 24576 floats

    const int tid  = threadIdx.x;
    const int wid  = tid >> 5;
    const int lane = tid & 31;
    const int warpRow = wid >> 2;        // 0..3
    const int warpCol = wid & 3;         // 0..3
    const int row0    = blockIdx.x * 64;

    wmma::fragment<wmma::accumulator, 16, 16, 8, float> acc[8];
    #pragma unroll
    for (int f = 0; f < 8; f++) wmma::fill_fragment(acc[f], 0.0f);

    // -------- tile loader: X(64x16) + W(512x16, stored j-major) ------------
    auto issue = [&](int k0, int buf) {
        if (tid < 256) {
            const int row = tid >> 2, q = tid & 3;
            cp_async16(&Xs[buf * 64 * ldX + row * ldX + q * 4],
                       X + (size_t)(row0 + row) * C_DIM + k0 + q * 4);
        }
        #pragma unroll
        for (int p = 0; p < 4; p++) {
            const int e = p * 512 + tid;
            const int j = e >> 2, q = e & 3;
            cp_async16(&Ws[buf * 512 * ldW + j * ldW + q * 4],
                       W + (size_t)j * C_DIM + k0 + q * 4);
        }
    };

    issue(0, 0);
    CP_COMMIT();
    int buf = 0;
    const int NIT = C_DIM / 16;          // 32
    for (int it = 0; it < NIT; ++it) {
        if (it + 1 < NIT) { issue((it + 1) * 16, buf ^ 1); CP_COMMIT(); CP_WAIT(1); }
        else              { CP_WAIT(0); }
        __syncthreads();

        const float* xb = &Xs[buf * 64 * ldX + (warpRow * 16) * ldX];
        const float* wb = &Ws[buf * 512 * ldW + (warpCol * 128) * ldW];
        #pragma unroll
        for (int kk = 0; kk < 16; kk += 8) {
            wmma::fragment<wmma::matrix_a, 16, 16, 8, wmma::precision::tf32, wmma::row_major> a;
            wmma::load_matrix_sync(a, xb + kk, ldX);
            #pragma unroll
            for (int t = 0; t < a.num_elements; t++) a.x[t] = wmma::__float_to_tf32(a.x[t]);
            #pragma unroll
            for (int f = 0; f < 8; f++) {
                wmma::fragment<wmma::matrix_b, 16, 16, 8, wmma::precision::tf32, wmma::col_major> b;
                wmma::load_matrix_sync(b, wb + f * 16 * ldW + kk, ldW);
                #pragma unroll
                for (int t = 0; t < b.num_elements; t++) b.x[t] = wmma::__float_to_tf32(b.x[t]);
                wmma::mma_sync(acc[f], a, b, acc[f]);
            }
        }
        __syncthreads();
        buf ^= 1;
    }

    // -------- epilogue: overlay SMEM as 64 x 520 tile -----------------------
    const int ldt = 520;
    #pragma unroll
    for (int f = 0; f < 8; f++)
        wmma::store_matrix_sync(&sm[(warpRow * 16) * ldt + warpCol * 128 + f * 16],
                                acc[f], ldt, wmma::mem_row_major);
    __syncthreads();

    #pragma unroll
    for (int rr = 0; rr < 4; rr++) {
        const int r = wid * 4 + rr;                  // 16 warps x 4 = 64 rows
        const size_t grow = (size_t)(row0 + r);
        float4 v[4];
        #pragma unroll
        for (int i = 0; i < 4; i++) {
            const int c4 = lane + i * 32;
            float4 t  = *(const float4*)&sm[r * ldt + c4 * 4];
            float4 bb = *(const float4*)&bias[c4 * 4];
            v[i] = make_float4(t.x + bb.x, t.y + bb.y, t.z + bb.z, t.w + bb.w);
        }
        if (DO_LN) {
            float s = 0.f, sq = 0.f;
            #pragma unroll
            for (int i = 0; i < 4; i++) {
                s  += v[i].x + v[i].y + v[i].z + v[i].w;
                sq += v[i].x * v[i].x + v[i].y * v[i].y + v[i].z * v[i].z + v[i].w * v[i].w;
            }
            #pragma unroll
            for (int o = 16; o > 0; o >>= 1) {
                s  += __shfl_xor_sync(0xffffffffu, s,  o);
                sq += __shfl_xor_sync(0xffffffffu, sq, o);
            }
            const float mu   = s * (1.0f / 512.0f);
            const float var  = sq * (1.0f / 512.0f) - mu * mu;
            const float rstd = rsqrtf(var + 1e-5f);
            #pragma unroll
            for (int i = 0; i < 4; i++) {
                const int c4 = lane + i * 32;
                float4 g  = *(const float4*)&gamma[c4 * 4];
                float4 be = *(const float4*)&beta [c4 * 4];
                float4 rz = *(const float4*)&resid[grow * C_DIM + c4 * 4];
                float4 o4;
                o4.x = (v[i].x - mu) * rstd * g.x + be.x + rz.x;
                o4.y = (v[i].y - mu) * rstd * g.y + be.y + rz.y;
                o4.z = (v[i].z - mu) * rstd * g.z + be.z + rz.z;
                o4.w = (v[i].w - mu) * rstd * g.w + be.w + rz.w;
                *(float4*)&out[grow * C_DIM + c4 * 4] = o4;
            }
        } else {
            #pragma unroll
            for (int i = 0; i < 4; i++) {
                const int c4 = lane + i * 32;
                *(float4*)&out[grow * C_DIM + c4 * 4] = v[i];
            }
        }
    }
}

// ============================================================================
// Linformer projection, split-K:
//   part[c,h,r,d] = sum_{n in chunk c} P[h,r,n] * S[n, h*64+d]
// Grid (NSPLIT, H), 256 threads. A tile 256x64 + B tile 64x64 staged via
// cp.async double buffer; 8 n-subtiles per chunk accumulated in registers.
// ============================================================================
__global__ void __launch_bounds__(256, 1)
proj_kernel(const float* __restrict__ P,
            const float* __restrict__ S,
            float* __restrict__ part)
{
    extern __shared__ float sm[];
    const int ldA = 72, ldB = 72;
    float* As = sm;                       // 2 * 256*72
    float* Bs = sm + 2 * 256 * ldA;       // 2 * 64*72

    const int tid = threadIdx.x;
    const int wid = tid >> 5;             // 0..7 -> rows wid*32
    const int h   = blockIdx.y;
    const int n0  = blockIdx.x * (N_NODES / NSPLIT);   // 512-wide chunk

    wmma::fragment<wmma::accumulator, 16, 16, 8, float> acc[2][4];
    #pragma unroll
    for (int i = 0; i < 2; i++)
        #pragma unroll
        for (int j = 0; j < 4; j++) wmma::fill_fragment(acc[i][j], 0.0f);

    auto issue = [&](int ns, int buf) {
        // A: P[h, r, n0+ns .. +64), 256 rows
        #pragma unroll
        for (int p = 0; p < 16; p++) {
            const int e = p * 256 + tid;
            const int row = e >> 4, q = e & 15;
            cp_async16(&As[buf * 256 * ldA + row * ldA + q * 4],
                       P + ((size_t)(h * K_RANK + row)) * N_NODES + n0 + ns + q * 4);
        }
        // B: S[n0+ns+row, h*64 .. +64), 64 rows
        #pragma unroll
        for (int p = 0; p < 4; p++) {
            const int e = p * 256 + tid;
            const int row = e >> 4, q = e & 15;
            cp_async16(&Bs[buf * 64 * ldB + row * ldB + q * 4],
                       S + (size_t)(n0 + ns + row) * C_DIM + h * D_HEAD + q * 4);
        }
    };

    issue(0, 0);
    CP_COMMIT();
    int buf = 0;
    const int NST = 8;                    // 512 / 64
    for (int st = 0; st < NST; ++st) {
        if (st + 1 < NST) { issue((st + 1) * 64, buf ^ 1); CP_COMMIT(); CP_WAIT(1); }
        else              { CP_WAIT(0); }
        __syncthreads();

        const float* ab = &As[buf * 256 * ldA + (wid * 32) * ldA];
        const float* bb = &Bs[buf * 64 * ldB];
        #pragma unroll
        for (int kk = 0; kk < 64; kk += 8) {
            wmma::fragment<wmma::matrix_a, 16, 16, 8, wmma::precision::tf32, wmma::row_major> a[2];
            #pragma unroll
            for (int i = 0; i < 2; i++) {
                wmma::load_matrix_sync(a[i], ab + (i * 16) * ldA + kk, ldA);
                #pragma unroll
                for (int t = 0; t < a[i].num_elements; t++) a[i].x[t] = wmma::__float_to_tf32(a[i].x[t]);
            }
            #pragma unroll
            for (int j = 0; j < 4; j++) {
                wmma::fragment<wmma::matrix_b, 16, 16, 8, wmma::precision::tf32, wmma::row_major> b;
                wmma::load_matrix_sync(b, bb + kk * ldB + j * 16, ldB);
                #pragma unroll
                for (int t = 0; t < b.num_elements; t++) b.x[t] = wmma::__float_to_tf32(b.x[t]);
                #pragma unroll
                for (int i = 0; i < 2; i++) wmma::mma_sync(acc[i][j], a[i], b, acc[i][j]);
            }
        }
        __syncthreads();
        buf ^= 1;
    }

    float* dst = part + ((size_t)blockIdx.x * H_HEADS + h) * K_RANK * D_HEAD;
    #pragma unroll
    for (int i = 0; i < 2; i++)
        #pragma unroll
        for (int j = 0; j < 4; j++)
            wmma::store_matrix_sync(dst + (wid * 32 + i * 16) * D_HEAD + j * 16,
                                    acc[i][j], D_HEAD, wmma::mem_row_major);
}

// Sum NSPLIT partials -> pK, pV
__global__ void proj_reduce_kernel(const float* __restrict__ partK,
                                   const float* __restrict__ partV,
                                   float* __restrict__ pK,
                                   float* __restrict__ pV)
{
    const int i = blockIdx.x * 256 + threadIdx.x;    // < H*K*D = 131072
    const int STRIDE = H_HEADS * K_RANK * D_HEAD;
    float sk = 0.f, sv = 0.f;
    #pragma unroll
    for (int c = 0; c < NSPLIT; c++) {
        sk += partK[(size_t)c * STRIDE + i];
        sv += partV[(size_t)c * STRIDE + i];
    }
    pK[i] = sk;
    pV[i] = sv;
}

// ============================================================================
// Attention: per (head, 64-node block) CTA. pK/pV resident in SMEM.
// ============================================================================
__global__ void attn_kernel(const float* __restrict__ Q,
                            const float* __restrict__ pK,
                            const float* __restrict__ pV,
                            float* __restrict__ attnout)
{
    extern __shared__ float smA[];
    float* pKs = smA;
    float* pVs = smA + K_RANK * D_HEAD;
    float* sc  = smA + 2 * K_RANK * D_HEAD;
    const int lds = 272;

    const int h   = blockIdx.y;
    const int n0  = blockIdx.x * 64;
    const int tid = threadIdx.x;
    const int wid = tid >> 5, lane = tid & 31;

    {
        const float4* s1 = (const float4*)(pK + (size_t)h * K_RANK * D_HEAD);
        const float4* s2 = (const float4*)(pV + (size_t)h * K_RANK * D_HEAD);
        float4* d1 = (float4*)pKs;
        float4* d2 = (float4*)pVs;
        for (int i = tid; i < K_RANK * D_HEAD / 4; i += 256) { d1[i] = s1[i]; d2[i] = s2[i]; }
    }
    __syncthreads();

    {   // GEMM1: scores 64x256
        const int wr = wid >> 1, wc = wid & 1;
        wmma::fragment<wmma::accumulator, 16, 16, 8, float> acc[8];
        #pragma unroll
        for (int f = 0; f < 8; f++) wmma::fill_fragment(acc[f], 0.0f);
        const float* Abase = Q + (size_t)(n0 + wr * 16) * C_DIM + h * D_HEAD;
        for (int k = 0; k < D_HEAD; k += 8) {
            wmma::fragment<wmma::matrix_a, 16, 16, 8, wmma::precision::tf32, wmma::row_major> a;
            wmma::load_matrix_sync(a, Abase + k, C_DIM);
            #pragma unroll
            for (int t = 0; t < a.num_elements; t++) a.x[t] = wmma::__float_to_tf32(a.x[t]);
            #pragma unroll
            for (int f = 0; f < 8; f++) {
                const int j0 = wc * 128 + f * 16;
                wmma::fragment<wmma::matrix_b, 16, 16, 8, wmma::precision::tf32, wmma::col_major> b;
                wmma::load_matrix_sync(b, pKs + j0 * D_HEAD + k, D_HEAD);
                #pragma unroll
                for (int t = 0; t < b.num_elements; t++) b.x[t] = wmma::__float_to_tf32(b.x[t]);
                wmma::mma_sync(acc[f], a, b, acc[f]);
            }
        }
        #pragma unroll
        for (int f = 0; f < 8; f++)
            wmma::store_matrix_sync(&sc[(wr * 16) * lds + wc * 128 + f * 16],
                                    acc[f], lds, wmma::mem_row_major);
    }
    __syncthreads();

    for (int r = wid; r < 64; r += 8) {   // softmax over 256
        float vals[8];
        float mx = -1e30f;
        #pragma unroll
        for (int i = 0; i < 8; i++) {
            vals[i] = sc[r * lds + lane + i * 32] * 0.125f;
            mx = fmaxf(mx, vals[i]);
        }
        #pragma unroll
        for (int o = 16; o > 0; o >>= 1) mx = fmaxf(mx, __shfl_xor_sync(0xffffffffu, mx, o));
        float ssum = 0.f;
        #pragma unroll
        for (int i = 0; i < 8; i++) { vals[i] = __expf(vals[i] - mx); ssum += vals[i]; }
        #pragma unroll
        for (int o = 16; o > 0; o >>= 1) ssum += __shfl_xor_sync(0xffffffffu, ssum, o);
        const float inv = 1.0f / ssum;
        #pragma unroll
        for (int i = 0; i < 8; i++) sc[r * lds + lane + i * 32] = vals[i] * inv;
    }
    __syncthreads();

    {   // GEMM2: out 64x64
        const int wr = wid >> 1, wc = wid & 1;
        wmma::fragment<wmma::accumulator, 16, 16, 8, float> acc[2];
        wmma::fill_fragment(acc[0], 0.0f);
        wmma::fill_fragment(acc[1], 0.0f);
        const float* Abase = sc + (wr * 16) * lds;
        for (int k = 0; k < K_RANK; k += 8) {
            wmma::fragment<wmma::matrix_a, 16, 16, 8, wmma::precision::tf32, wmma::row_major> a;
            wmma::load_matrix_sync(a, Abase + k, lds);
            #pragma unroll
            for (int t = 0; t < a.num_elements; t++) a.x[t] = wmma::__float_to_tf32(a.x[t]);
            #pragma unroll
            for (int f = 0; f < 2; f++) {
                wmma::fragment<wmma::matrix_b, 16, 16, 8, wmma::precision::tf32, wmma::row_major> b;
                wmma::load_matrix_sync(b, pVs + k * D_HEAD + wc * 32 + f * 16, D_HEAD);
                #pragma unroll
                for (int t = 0; t < b.num_elements; t++) b.x[t] = wmma::__float_to_tf32(b.x[t]);
                wmma::mma_sync(acc[f], a, b, acc[f]);
            }
        }
        #pragma unroll
        for (int f = 0; f < 2; f++)
            wmma::store_matrix_sync(attnout + (size_t)(n0 + wr * 16) * C_DIM
                                            + h * D_HEAD + wc * 32 + f * 16,
                                    acc[f], C_DIM, wmma::mem_row_major);
    }
}

// ============================================================================
// Node epilogue: out = LN(attnout) * g + b + node_feats. One warp per row.
// ============================================================================
__global__ void ln_resid_kernel(const float* __restrict__ X,
                                const float* __restrict__ resid,
                                const float* __restrict__ gamma,
                                const float* __restrict__ beta,
                                float* __restrict__ out)
{
    const int wid = threadIdx.x >> 5, lane = threadIdx.x & 31;
    const size_t row = (size_t)blockIdx.x * 8 + wid;
    float4 v[4];
    float s = 0.f, sq = 0.f;
    #pragma unroll
    for (int i = 0; i < 4; i++) {
        const int c4 = lane + i * 32;
        v[i] = *(const float4*)&X[row * C_DIM + c4 * 4];
        s  += v[i].x + v[i].y + v[i].z + v[i].w;
        sq += v[i].x * v[i].x + v[i].y * v[i].y + v[i].z * v[i].z + v[i].w * v[i].w;
    }
    #pragma unroll
    for (int o = 16; o > 0; o >>= 1) {
        s  += __shfl_xor_sync(0xffffffffu, s,  o);
        sq += __shfl_xor_sync(0xffffffffu, sq, o);
    }
    const float mu   = s * (1.0f / 512.0f);
    const float var  = sq * (1.0f / 512.0f) - mu * mu;
    const float rstd = rsqrtf(var + 1e-5f);
    #pragma unroll
    for (int i = 0; i < 4; i++) {
        const int c4 = lane + i * 32;
        float4 g  = *(const float4*)&gamma[c4 * 4];
        float4 be = *(const float4*)&beta [c4 * 4];
        float4 rz = *(const float4*)&resid[row * C_DIM + c4 * 4];
        float4 o4;
        o4.x = (v[i].x - mu) * rstd * g.x + be.x + rz.x;
        o4.y = (v[i].y - mu) * rstd * g.y + be.y + rz.y;
        o4.z = (v[i].z - mu) * rstd * g.z + be.z + rz.z;
        o4.w = (v[i].w - mu) * rstd * g.w + be.w + rz.w;
        *(float4*)&out[row * C_DIM + c4 * 4] = o4;
    }
}

// ============================================================================
extern "C" void kernel_launch(void* const* d_in, const int* in_sizes, int n_in,
                              void* d_out, int out_size)
{
    const float* node = (const float*)d_in[0];
    const float* edge = (const float*)d_in[1];
    const float* Wq   = (const float*)d_in[2];
    const float* bq   = (const float*)d_in[3];
    const float* Wk   = (const float*)d_in[4];
    const float* bk   = (const float*)d_in[5];
    const float* Wv   = (const float*)d_in[6];
    const float* bv   = (const float*)d_in[7];
    const float* We   = (const float*)d_in[8];
    const float* be   = (const float*)d_in[9];
    const float* Ep   = (const float*)d_in[10];
    const float* Fp   = (const float*)d_in[11];
    const float* lng  = (const float*)d_in[12];
    const float* lnb  = (const float*)d_in[13];
    const float* leg  = (const float*)d_in[14];
    const float* leb  = (const float*)d_in[15];
    float* out = (float*)d_out;

    float *pQ, *pK_, *pV_, *pAt, *ppK, *ppV, *ppaK, *ppaV;
    cudaGetSymbolAddress((void**)&pQ,   d_Q);
    cudaGetSymbolAddress((void**)&pK_,  d_Kmat);
    cudaGetSymbolAddress((void**)&pV_,  d_Vmat);
    cudaGetSymbolAddress((void**)&pAt,  d_Att);
    cudaGetSymbolAddress((void**)&ppK,  d_pK);
    cudaGetSymbolAddress((void**)&ppV,  d_pV);
    cudaGetSymbolAddress((void**)&ppaK, d_partK);
    cudaGetSymbolAddress((void**)&ppaV, d_partV);

    const int SM_LIN  = 64 * 520 * (int)sizeof(float);                          // 133120 (>= GEMM stage bufs)
    const int SM_PROJ = (2 * 256 * 72 + 2 * 64 * 72) * (int)sizeof(float);      // 184320
    const int SM_ATT  = (2 * K_RANK * D_HEAD + 64 * 272) * (int)sizeof(float);  // 200704
    cudaFuncSetAttribute(linear512_kernel<false>, cudaFuncAttributeMaxDynamicSharedMemorySize, SM_LIN);
    cudaFuncSetAttribute(linear512_kernel<true>,  cudaFuncAttributeMaxDynamicSharedMemorySize, SM_LIN);
    cudaFuncSetAttribute(proj_kernel,             cudaFuncAttributeMaxDynamicSharedMemorySize, SM_PROJ);
    cudaFuncSetAttribute(attn_kernel,             cudaFuncAttributeMaxDynamicSharedMemorySize, SM_ATT);

    // 1) QKV projections (N x 512 each)
    linear512_kernel<false><<<N_NODES / 64, 512, SM_LIN>>>(node, Wq, bq, nullptr, nullptr, nullptr, pQ);
    linear512_kernel<false><<<N_NODES / 64, 512, SM_LIN>>>(node, Wk, bk, nullptr, nullptr, nullptr, pK_);
    linear512_kernel<false><<<N_NODES / 64, 512, SM_LIN>>>(node, Wv, bv, nullptr, nullptr, nullptr, pV_);

    // 2) Linformer projections: split-K partials + reduce
    proj_kernel<<<dim3(NSPLIT, H_HEADS), 256, SM_PROJ>>>(Ep, pK_, ppaK);
    proj_kernel<<<dim3(NSPLIT, H_HEADS), 256, SM_PROJ>>>(Fp, pV_, ppaV);
    proj_reduce_kernel<<<(H_HEADS * K_RANK * D_HEAD) / 256, 256>>>(ppaK, ppaV, ppK, ppV);

    // 3) Attention per (head, 64-row block)
    attn_kernel<<<dim3(N_NODES / 64, H_HEADS), 256, SM_ATT>>>(pQ, ppK, ppV, pAt);

    // 4) Node output: LN(attn) + node_feats -> out[0 : N*512)
    ln_resid_kernel<<<N_NODES / 8, 256>>>(pAt, node, lng, lnb, out);

    // 5) Edge path: LN(edge @ We^T + be) + edge_feats -> out[N*512 : )
    linear512_kernel<true><<<E_EDGES / 64, 512, SM_LIN>>>(
        edge, We, be, edge, leg, leb, out + (size_t)N_NODES * C_DIM);
}